// round 2
// baseline (speedup 1.0000x reference)
#include <cuda_runtime.h>

// FFT long conv: y[b, 0:L] = (1/N) * circular_conv_N(x_padded, h_padded), N = 2L = 16384.
// One CTA per row. Pack z = x + i*h, forward radix-4 DIF FFT (digit-reversed out),
// combine spectra + pointwise product in digit-reversed domain, radix-4 DIT inverse
// (digit-reversed in -> natural out), emit real part * 1/N^2.

#define L_SIG  8192
#define N_FFT  16384
#define NTHREADS 1024
#define SMEM_BYTES (N_FFT * 8)

__device__ __forceinline__ float2 cadd(float2 a, float2 b) { return make_float2(a.x + b.x, a.y + b.y); }
__device__ __forceinline__ float2 csub(float2 a, float2 b) { return make_float2(a.x - b.x, a.y - b.y); }
__device__ __forceinline__ float2 cmul(float2 a, float2 b) {
    return make_float2(fmaf(a.x, b.x, -a.y * b.y), fmaf(a.x, b.y, a.y * b.x));
}

// reverse the seven base-4 digits of a 14-bit index
__device__ __forceinline__ int rev4_14(int v) {
    unsigned r = __brev((unsigned)v) >> 18;            // full 14-bit bit reversal
    return (int)(((r & 0x2AAAu) >> 1) | ((r & 0x1555u) << 1));  // swap bits within pairs
}

__global__ __launch_bounds__(NTHREADS, 1)
void fftconv_kernel(const float* __restrict__ x, const float* __restrict__ h,
                    float* __restrict__ y) {
    extern __shared__ float2 z[];   // N_FFT complex
    const int row = blockIdx.x;
    const int tid = threadIdx.x;
    const float* xr = x + (size_t)row * L_SIG;
    const float* hr = h + (size_t)row * L_SIG;

    // ---- load: z = x + i*h, zero-padded to N ----
    #pragma unroll
    for (int j = tid; j < L_SIG; j += NTHREADS) {
        z[j]          = make_float2(xr[j], hr[j]);
        z[j + L_SIG]  = make_float2(0.0f, 0.0f);
    }
    __syncthreads();

    // ---- forward radix-4 DIF: natural in -> base4-digit-reversed out ----
    #pragma unroll
    for (int s = 0; s < 7; s++) {
        const int m = N_FFT >> (2 * s + 2);    // 4096 ... 1
        const float tstep = -6.2831853071795864f / (float)(4 * m);
        #pragma unroll
        for (int it = 0; it < (N_FFT / 4) / NTHREADS; it++) {
            int idx = tid + it * NTHREADS;
            int j = idx & (m - 1);
            int base = (idx - j) << 2;
            float2 a0 = z[base + j];
            float2 a1 = z[base + j + m];
            float2 a2 = z[base + j + 2 * m];
            float2 a3 = z[base + j + 3 * m];

            float2 t0 = cadd(a0, a2), t1 = csub(a0, a2);
            float2 t2 = cadd(a1, a3), t3 = csub(a1, a3);
            // forward DFT4 (w4 = -i)
            float2 y0 = cadd(t0, t2);
            float2 y2 = csub(t0, t2);
            float2 y1 = make_float2(t1.x + t3.y, t1.y - t3.x);  // t1 - i*t3
            float2 y3 = make_float2(t1.x - t3.y, t1.y + t3.x);  // t1 + i*t3

            float sn, cs;
            __sincosf(tstep * (float)j, &sn, &cs);
            float2 w1 = make_float2(cs, sn);      // e^{-2pi i j/(4m)}
            float2 w2 = cmul(w1, w1);
            float2 w3 = cmul(w2, w1);

            z[base + j]         = y0;
            z[base + j + m]     = cmul(y1, w1);
            z[base + j + 2 * m] = cmul(y2, w2);
            z[base + j + 3 * m] = cmul(y3, w3);
        }
        __syncthreads();
    }

    // ---- combine: X[k]*H[k] pointwise, operating in digit-reversed positions ----
    // z[p] currently holds Z[rev4(p)]. For each freq pair (k, N-k):
    //   X[k] = (Z[k]+conj(Z[N-k]))/2 ; H[k] = -i(Z[k]-conj(Z[N-k]))/2 ; Y[k]=X*H ; Y[N-k]=conj(Y[k])
    for (int k = tid; k <= N_FFT / 2; k += NTHREADS) {
        if (k == 0) {
            float2 Z0 = z[0];                       // Z[0] = X0 + i*H0 (both real)
            z[0] = make_float2(Z0.x * Z0.y, 0.0f);
        } else if (k == N_FFT / 2) {
            int p = rev4_14(N_FFT / 2);
            float2 Zn = z[p];                       // Z[N/2] = Xn + i*Hn (both real)
            z[p] = make_float2(Zn.x * Zn.y, 0.0f);
        } else {
            int pa = rev4_14(k);
            int pb = rev4_14(N_FFT - k);
            float2 Za = z[pa];
            float2 Zb = z[pb];
            float2 X = make_float2(0.5f * (Za.x + Zb.x), 0.5f * (Za.y - Zb.y));
            float2 H = make_float2(0.5f * (Za.y + Zb.y), 0.5f * (Zb.x - Za.x));
            float2 Y = cmul(X, H);
            z[pa] = Y;
            z[pb] = make_float2(Y.x, -Y.y);         // Y[N-k] = conj(Y[k])
        }
    }
    __syncthreads();

    // ---- inverse radix-4 DIT: digit-reversed in -> natural out (no 1/N here) ----
    #pragma unroll
    for (int s = 0; s < 7; s++) {
        const int m = 1 << (2 * s);                // 1 ... 4096
        const float tstep = 6.2831853071795864f / (float)(4 * m);
        #pragma unroll
        for (int it = 0; it < (N_FFT / 4) / NTHREADS; it++) {
            int idx = tid + it * NTHREADS;
            int j = idx & (m - 1);
            int base = (idx - j) << 2;

            float sn, cs;
            __sincosf(tstep * (float)j, &sn, &cs);
            float2 w1 = make_float2(cs, sn);       // e^{+2pi i j/(4m)}
            float2 w2 = cmul(w1, w1);
            float2 w3 = cmul(w2, w1);

            float2 a0 = z[base + j];
            float2 a1 = cmul(z[base + j + m], w1);
            float2 a2 = cmul(z[base + j + 2 * m], w2);
            float2 a3 = cmul(z[base + j + 3 * m], w3);

            float2 t0 = cadd(a0, a2), t1 = csub(a0, a2);
            float2 t2 = cadd(a1, a3), t3 = csub(a1, a3);
            // inverse DFT4 (w4 = +i)
            z[base + j]         = cadd(t0, t2);
            z[base + j + 2 * m] = csub(t0, t2);
            z[base + j + m]     = make_float2(t1.x - t3.y, t1.y + t3.x);  // t1 + i*t3
            z[base + j + 3 * m] = make_float2(t1.x + t3.y, t1.y - t3.x);  // t1 - i*t3
        }
        __syncthreads();
    }

    // ---- store: y = Re(result) * 1/N^2  (forward-norm rfft pair => conv/N overall) ----
    const float scale = 1.0f / ((float)N_FFT * (float)N_FFT);
    float* yr = y + (size_t)row * L_SIG;
    #pragma unroll
    for (int j = tid; j < L_SIG; j += NTHREADS) {
        yr[j] = z[j].x * scale;
    }
}

extern "C" void kernel_launch(void* const* d_in, const int* in_sizes, int n_in,
                              void* d_out, int out_size) {
    const float* x = (const float*)d_in[0];
    const float* h = (const float*)d_in[1];
    float* y = (float*)d_out;

    cudaFuncSetAttribute(fftconv_kernel,
                         cudaFuncAttributeMaxDynamicSharedMemorySize, SMEM_BYTES);

    const int B = in_sizes[0] / L_SIG;   // 4096 rows
    fftconv_kernel<<<B, NTHREADS, SMEM_BYTES>>>(x, h, y);
}

// round 7
// speedup vs baseline: 2.9556x; 2.9556x over previous
#include <cuda_runtime.h>

// FFT long conv, N = 16384 = 4^7, one CTA per row.
// Forward: 3 radix-16 (register) DIF passes (s = 1024, 64, 4).
// Middle: fused pass = fwd radix-4 (m=1, twiddle-free) + spectral combine
//         (quad-pair c <-> c') + inv radix-4 (m=1, twiddle-free).
// Inverse: 3 radix-16 DIT passes (s = 4, 64, 1024).
// SMEM uses skewed layout phys(i) = i + (i>>4) -> conflict-free LDS.64 in all passes.
// (R6: resubmission after GB300 container infra failure; source re-audited, unchanged.)

#define L_SIG  8192
#define N_FFT  16384
#define NT     512
#define SMEM_F2 (N_FFT + (N_FFT >> 4))     // 17408 float2
#define SMEM_BYTES (SMEM_F2 * 8)           // 139264 B

__device__ __forceinline__ int SKEW(int i) { return i + (i >> 4); }

__device__ __forceinline__ float2 cadd(float2 a, float2 b) { return make_float2(a.x + b.x, a.y + b.y); }
__device__ __forceinline__ float2 csub(float2 a, float2 b) { return make_float2(a.x - b.x, a.y - b.y); }
__device__ __forceinline__ float2 cmul(float2 a, float2 b) {
    return make_float2(fmaf(a.x, b.x, -a.y * b.y), fmaf(a.x, b.y, a.y * b.x));
}
__device__ __forceinline__ float2 cconj(float2 a) { return make_float2(a.x, -a.y); }

// reverse six base-4 digits of a 12-bit value
__device__ __forceinline__ int rev6_base4(int c) {
    unsigned r = __brev((unsigned)c) >> 20;
    return (int)(((r & 0xAAAu) >> 1) | ((r & 0x555u) << 1));
}

__device__ __forceinline__ void dft4_fwd(float2& a0, float2& a1, float2& a2, float2& a3) {
    float2 t0 = cadd(a0, a2), t1 = csub(a0, a2), t2 = cadd(a1, a3), t3 = csub(a1, a3);
    a0 = cadd(t0, t2); a2 = csub(t0, t2);
    a1 = make_float2(t1.x + t3.y, t1.y - t3.x);   // t1 - i*t3
    a3 = make_float2(t1.x - t3.y, t1.y + t3.x);   // t1 + i*t3
}
__device__ __forceinline__ void dft4_inv(float2& a0, float2& a1, float2& a2, float2& a3) {
    float2 t0 = cadd(a0, a2), t1 = csub(a0, a2), t2 = cadd(a1, a3), t3 = csub(a1, a3);
    a0 = cadd(t0, t2); a2 = csub(t0, t2);
    a1 = make_float2(t1.x - t3.y, t1.y + t3.x);   // t1 + i*t3
    a3 = make_float2(t1.x + t3.y, t1.y - t3.x);   // t1 - i*t3
}

// omega16^k = e^{-+ 2*pi*i*k/16}; k is compile-time after unroll (k in {0..9})
__device__ __forceinline__ float2 om16(int k, bool inv) {
    const float OC[10] = {1.f, 0.9238795325f, 0.7071067812f, 0.3826834324f, 0.f,
                          0.f, -0.7071067812f, 0.f, 0.f, -0.9238795325f};
    const float OS[10] = {0.f, 0.3826834324f, 0.7071067812f, 0.9238795325f, 1.f,
                          0.f, 0.7071067812f, 0.f, 0.f, -0.3826834324f};
    return make_float2(OC[k], inv ? OS[k] : -OS[k]);
}

// Radix-16 pass at stride S. Forward DIF: levels (m=4S) then (m=S).
// Inverse DIT: levels (m=S) then (m=4S). 16 points per thread in registers.
template<int S, bool INV>
__device__ __forceinline__ void radix16_pass(float2* z, int tid) {
    const float ang0 = (INV ? 6.2831853071795864f : -6.2831853071795864f) / (16.0f * (float)S);
    #pragma unroll
    for (int it = 0; it < (N_FFT / 16) / NT; it++) {
        const int idx = tid + it * NT;
        const int j = idx & (S - 1);
        const int base = (idx / S) * (16 * S) + j;

        float2 b[16];
        #pragma unroll
        for (int r = 0; r < 16; r++) b[r] = z[SKEW(base + S * r)];

        float sn, cs;
        __sincosf(ang0 * (float)j, &sn, &cs);
        const float2 W   = make_float2(cs, sn);
        const float2 W2  = cmul(W, W);
        const float2 W3  = cmul(W2, W);
        const float2 W4  = cmul(W2, W2);
        const float2 W8  = cmul(W4, W4);
        const float2 W12 = cmul(W8, W4);

        if (!INV) {
            #pragma unroll
            for (int r0 = 0; r0 < 4; r0++) {     // level m = 4S
                float2 a0 = b[r0], a1 = b[r0 + 4], a2 = b[r0 + 8], a3 = b[r0 + 12];
                dft4_fwd(a0, a1, a2, a3);
                b[r0]      = a0;
                b[r0 + 4]  = cmul(a1, r0 ? cmul(W,  om16(r0,     false)) : W);
                b[r0 + 8]  = cmul(a2, r0 ? cmul(W2, om16(2 * r0, false)) : W2);
                b[r0 + 12] = cmul(a3, r0 ? cmul(W3, om16(3 * r0, false)) : W3);
            }
            #pragma unroll
            for (int d = 0; d < 4; d++) {        // level m = S
                float2 a0 = b[4*d], a1 = b[4*d+1], a2 = b[4*d+2], a3 = b[4*d+3];
                dft4_fwd(a0, a1, a2, a3);
                b[4*d]   = a0;
                b[4*d+1] = cmul(a1, W4);
                b[4*d+2] = cmul(a2, W8);
                b[4*d+3] = cmul(a3, W12);
            }
        } else {
            #pragma unroll
            for (int d = 0; d < 4; d++) {        // level m = S
                float2 a0 = b[4*d];
                float2 a1 = cmul(b[4*d+1], W4);
                float2 a2 = cmul(b[4*d+2], W8);
                float2 a3 = cmul(b[4*d+3], W12);
                dft4_inv(a0, a1, a2, a3);
                b[4*d] = a0; b[4*d+1] = a1; b[4*d+2] = a2; b[4*d+3] = a3;
            }
            #pragma unroll
            for (int r0 = 0; r0 < 4; r0++) {     // level m = 4S
                float2 a0 = b[r0];
                float2 a1 = cmul(b[r0 + 4],  r0 ? cmul(W,  om16(r0,     true)) : W);
                float2 a2 = cmul(b[r0 + 8],  r0 ? cmul(W2, om16(2 * r0, true)) : W2);
                float2 a3 = cmul(b[r0 + 12], r0 ? cmul(W3, om16(3 * r0, true)) : W3);
                dft4_inv(a0, a1, a2, a3);
                b[r0] = a0; b[r0 + 4] = a1; b[r0 + 8] = a2; b[r0 + 12] = a3;
            }
        }

        #pragma unroll
        for (int r = 0; r < 16; r++) z[SKEW(base + S * r)] = b[r];
    }
}

// Fused: fwd radix-4 (m=1) + combine + inv radix-4 (m=1).
// Quad c (positions 4c..4c+3) holds, after fwd DFT4, Z[4096*t + k0] with k0 = rev6(c).
// Conjugate partner quad: c' = rev6(4096 - k0), pairing (c,t) <-> (c',3-t).
__device__ __forceinline__ void fused_mid(float2* z, int tid) {
    for (int c = tid; c < N_FFT / 4; c += NT) {
        if (c == 0) {
            float2 A0 = z[SKEW(0)], A1 = z[SKEW(1)], A2 = z[SKEW(2)], A3 = z[SKEW(3)];
            dft4_fwd(A0, A1, A2, A3);            // freqs 0, 4096, 8192, 12288
            float2 Y0 = make_float2(A0.x * A0.y, 0.0f);       // DC: both real
            float2 Y2 = make_float2(A2.x * A2.y, 0.0f);       // Nyquist: both real
            float2 Za = A1, Zb = A3;                           // 4096 <-> 12288
            float2 X = make_float2(0.5f * (Za.x + Zb.x), 0.5f * (Za.y - Zb.y));
            float2 H = make_float2(0.5f * (Za.y + Zb.y), 0.5f * (Zb.x - Za.x));
            float2 Y1 = cmul(X, H);
            float2 Y3 = cconj(Y1);
            dft4_inv(Y0, Y1, Y2, Y3);
            z[SKEW(0)] = Y0; z[SKEW(1)] = Y1; z[SKEW(2)] = Y2; z[SKEW(3)] = Y3;
            continue;
        }
        const int k0 = rev6_base4(c);
        const int cp = rev6_base4(4096 - k0);
        if (c > cp) continue;                    // partner thread handles it (c==cp: self)

        float2 A[4], B[4];
        #pragma unroll
        for (int t = 0; t < 4; t++) A[t] = z[SKEW(4 * c + t)];
        #pragma unroll
        for (int t = 0; t < 4; t++) B[t] = z[SKEW(4 * cp + t)];

        dft4_fwd(A[0], A[1], A[2], A[3]);
        dft4_fwd(B[0], B[1], B[2], B[3]);

        float2 An[4], Bn[4];
        #pragma unroll
        for (int t = 0; t < 4; t++) {
            float2 Za = A[t], Zb = B[3 - t];
            float2 X = make_float2(0.5f * (Za.x + Zb.x), 0.5f * (Za.y - Zb.y));
            float2 H = make_float2(0.5f * (Za.y + Zb.y), 0.5f * (Zb.x - Za.x));
            float2 Y = cmul(X, H);
            An[t] = Y;
            Bn[3 - t] = cconj(Y);
        }

        dft4_inv(An[0], An[1], An[2], An[3]);
        dft4_inv(Bn[0], Bn[1], Bn[2], Bn[3]);

        #pragma unroll
        for (int t = 0; t < 4; t++) z[SKEW(4 * c + t)] = An[t];
        #pragma unroll
        for (int t = 0; t < 4; t++) z[SKEW(4 * cp + t)] = Bn[t];
    }
}

__global__ __launch_bounds__(NT, 1)
void fftconv_kernel(const float* __restrict__ x, const float* __restrict__ h,
                    float* __restrict__ y) {
    extern __shared__ float2 z[];
    const int row = blockIdx.x;
    const int tid = threadIdx.x;

    const float4* x4 = (const float4*)(x + (size_t)row * L_SIG);
    const float4* h4 = (const float4*)(h + (size_t)row * L_SIG);

    #pragma unroll
    for (int j = tid; j < L_SIG / 4; j += NT) {
        float4 xv = x4[j], hv = h4[j];
        z[SKEW(4 * j + 0)] = make_float2(xv.x, hv.x);
        z[SKEW(4 * j + 1)] = make_float2(xv.y, hv.y);
        z[SKEW(4 * j + 2)] = make_float2(xv.z, hv.z);
        z[SKEW(4 * j + 3)] = make_float2(xv.w, hv.w);
    }
    #pragma unroll
    for (int j = tid; j < L_SIG; j += NT)
        z[SKEW(L_SIG + j)] = make_float2(0.0f, 0.0f);
    __syncthreads();

    radix16_pass<1024, false>(z, tid); __syncthreads();
    radix16_pass<64,   false>(z, tid); __syncthreads();
    radix16_pass<4,    false>(z, tid); __syncthreads();
    fused_mid(z, tid);                 __syncthreads();
    radix16_pass<4,    true >(z, tid); __syncthreads();
    radix16_pass<64,   true >(z, tid); __syncthreads();
    radix16_pass<1024, true >(z, tid); __syncthreads();

    const float scale = 1.0f / ((float)N_FFT * (float)N_FFT);
    float4* y4 = (float4*)(y + (size_t)row * L_SIG);
    #pragma unroll
    for (int j = tid; j < L_SIG / 4; j += NT) {
        float2 v0 = z[SKEW(4 * j + 0)];
        float2 v1 = z[SKEW(4 * j + 1)];
        float2 v2 = z[SKEW(4 * j + 2)];
        float2 v3 = z[SKEW(4 * j + 3)];
        y4[j] = make_float4(v0.x * scale, v1.x * scale, v2.x * scale, v3.x * scale);
    }
}

extern "C" void kernel_launch(void* const* d_in, const int* in_sizes, int n_in,
                              void* d_out, int out_size) {
    const float* x = (const float*)d_in[0];
    const float* h = (const float*)d_in[1];
    float* y = (float*)d_out;

    cudaFuncSetAttribute(fftconv_kernel,
                         cudaFuncAttributeMaxDynamicSharedMemorySize, SMEM_BYTES);

    const int B = in_sizes[0] / L_SIG;   // 4096 rows
    fftconv_kernel<<<B, NT, SMEM_BYTES>>>(x, h, y);
}